// round 14
// baseline (speedup 1.0000x reference)
#include <cuda_runtime.h>
#include <cuda_bf16.h>
#include <cuda_fp16.h>
#include <cstdint>
#include <math.h>

#define HIDDEN 512
#define E_DIM  1024
#define S_DIM  128
#define NB     32
#define NSEQ   1024
#define BTOK   (NB * NSEQ)
#define UVC    (2 * E_DIM + S_DIM)   // 2176
#define HALF   64

#define TM 128
#define TN 128
#define TKC 32                        // K elements per chunk (2B each)
#define RSTR 64                       // smem row stride (bytes, swizzled)
// bf16 3-term core regions
#define AHI 0
#define ALO 8192
#define BHI 16384
#define BLO 24576
#define BUF_BYTES 32768
#define NSTAGE 3
#define SMEM_TOTAL (NSTAGE * BUF_BYTES)     // 98304
// fp16 single-A dual-B core regions
#define SD_AS  0
#define SD_BH  8192
#define SD_BL  16384
#define SD_BUF 24576
#define SD_SMEM (NSTAGE * SD_BUF)           // 73728

typedef __nv_bfloat16 bf16;
typedef __half        fp16;

// ---------------- scratch (device globals) ---------------------------------
__device__ float g_uv[(size_t)BTOK * UVC];
__device__ bf16  g_xs_hi[(size_t)BTOK * HIDDEN];
__device__ bf16  g_xs_lo[(size_t)BTOK * HIDDEN];
__device__ bf16  g_WuvT_hi[(size_t)UVC * HIDDEN];
__device__ bf16  g_WuvT_lo[(size_t)UVC * HIDDEN];
__device__ fp16  g_WoT_h[(size_t)HIDDEN * E_DIM];
__device__ fp16  g_WoT_l[(size_t)HIDDEN * E_DIM];
__device__ bf16  g_q_hi[BTOK * S_DIM];
__device__ bf16  g_q_lo[BTOK * S_DIM];
__device__ bf16  g_k_hi[BTOK * S_DIM];
__device__ bf16  g_k_lo[BTOK * S_DIM];
__device__ fp16  g_s_h[(size_t)NB * NSEQ * NSEQ];     // scores, single fp16
__device__ fp16  g_vT_h[(size_t)NB * E_DIM * NSEQ];
__device__ fp16  g_vT_l[(size_t)NB * E_DIM * NSEQ];
__device__ fp16  g_attn_h[(size_t)BTOK * E_DIM];      // attn, single fp16
__device__ float g_sinT[NSEQ * HALF];
__device__ float g_cosT[NSEQ * HALF];

extern __shared__ char dyn_smem[];

// ---------------- PTX helpers ----------------------------------------------
__device__ __forceinline__ uint32_t smem_u32(const void* p) {
    uint32_t a;
    asm("{ .reg .u64 t; cvta.to.shared.u64 t, %1; cvt.u32.u64 %0, t; }"
        : "=r"(a) : "l"(p));
    return a;
}
__device__ __forceinline__ void ldm_x4(uint32_t* r, uint32_t addr) {
    asm volatile("ldmatrix.sync.aligned.m8n8.x4.shared.b16 {%0,%1,%2,%3}, [%4];"
        : "=r"(r[0]), "=r"(r[1]), "=r"(r[2]), "=r"(r[3]) : "r"(addr));
}
__device__ __forceinline__ void mma_bf16(float* d, const uint32_t* a, const uint32_t* b) {
    asm volatile(
        "mma.sync.aligned.m16n8k16.row.col.f32.bf16.bf16.f32 "
        "{%0,%1,%2,%3}, {%4,%5,%6,%7}, {%8,%9}, {%0,%1,%2,%3};"
        : "+f"(d[0]), "+f"(d[1]), "+f"(d[2]), "+f"(d[3])
        : "r"(a[0]), "r"(a[1]), "r"(a[2]), "r"(a[3]), "r"(b[0]), "r"(b[1]));
}
__device__ __forceinline__ void mma_fp16(float* d, const uint32_t* a, const uint32_t* b) {
    asm volatile(
        "mma.sync.aligned.m16n8k16.row.col.f32.f16.f16.f32 "
        "{%0,%1,%2,%3}, {%4,%5,%6,%7}, {%8,%9}, {%0,%1,%2,%3};"
        : "+f"(d[0]), "+f"(d[1]), "+f"(d[2]), "+f"(d[3])
        : "r"(a[0]), "r"(a[1]), "r"(a[2]), "r"(a[3]), "r"(b[0]), "r"(b[1]));
}
#define CP16(dst, src) \
    asm volatile("cp.async.cg.shared.global [%0], [%1], 16;" :: "r"(dst), "l"(src))
#define CP_COMMIT() asm volatile("cp.async.commit_group;" ::: "memory")
#define CP_WAIT(n)  asm volatile("cp.async.wait_group %0;" :: "n"(n) : "memory")

// swizzle: row r, 16B-chunk j -> byte offset within region
__device__ __forceinline__ uint32_t swz_off(int row, int chunk) {
    return (uint32_t)(row * RSTR) + (uint32_t)((chunk ^ ((row >> 1) & 3)) << 4);
}

// fp32 -> bf16 hi/lo
__device__ __forceinline__ void split1(float v, bf16& h, bf16& l) {
    h = __float2bfloat16(v);
    l = __float2bfloat16(v - __bfloat162float(h));
}
__device__ __forceinline__ void split2(float a, float b, uint32_t& hi, uint32_t& lo) {
    bf16 h0, l0, h1, l1;
    split1(a, h0, l0);
    split1(b, h1, l1);
    hi = ((uint32_t)__bfloat16_as_ushort(h1) << 16) | __bfloat16_as_ushort(h0);
    lo = ((uint32_t)__bfloat16_as_ushort(l1) << 16) | __bfloat16_as_ushort(l0);
}
// fp32 -> fp16 hi/lo
__device__ __forceinline__ void split1h(float v, fp16& h, fp16& l) {
    h = __float2half(v);
    l = __float2half(v - __half2float(h));
}
__device__ __forceinline__ uint32_t pack_h2(float a, float b) {
    __half2 p = __floats2half2_rn(a, b);
    return *(uint32_t*)&p;
}

// ---------------- core 1: bf16 3-term (A,B both hi/lo) ---------------------
template <class Epi>
__device__ __forceinline__ void gemm_core(const bf16* __restrict__ Ahi,
                                          const bf16* __restrict__ Alo, int lda,
                                          const bf16* __restrict__ Bhi,
                                          const bf16* __restrict__ Blo, int ldb,
                                          int K, Epi epi) {
    const int tid  = threadIdx.x;
    const int lane = tid & 31;
    const int wid  = tid >> 5;
    const int wm   = wid >> 2;
    const int wn   = wid & 3;
    const int g    = lane >> 2;
    const int tg   = lane & 3;
    const int lrow = lane & 15;
    const int lchunk = lane >> 4;
    const uint32_t sbase = smem_u32(dyn_smem);

    const int srow = tid >> 1;
    const int sh   = tid & 1;
    const uint32_t so0 = swz_off(srow, sh * 2);
    const uint32_t so1 = swz_off(srow, sh * 2 + 1);
    const size_t aoff = (size_t)srow * lda + sh * 16;
    const size_t boff = (size_t)srow * ldb + sh * 16;

    float acc[4][4][4];
    #pragma unroll
    for (int i = 0; i < 4; i++)
        #pragma unroll
        for (int j = 0; j < 4; j++)
            #pragma unroll
            for (int t = 0; t < 4; t++) acc[i][j][t] = 0.f;

    const int NC = K / TKC;

    auto stage = [&](int buf, int c) {
        uint32_t d = sbase + buf * BUF_BYTES;
        int ko = c * TKC;
        CP16(d + AHI + so0, Ahi + aoff + ko);
        CP16(d + AHI + so1, Ahi + aoff + ko + 8);
        CP16(d + ALO + so0, Alo + aoff + ko);
        CP16(d + ALO + so1, Alo + aoff + ko + 8);
        CP16(d + BHI + so0, Bhi + boff + ko);
        CP16(d + BHI + so1, Bhi + boff + ko + 8);
        CP16(d + BLO + so0, Blo + boff + ko);
        CP16(d + BLO + so1, Blo + boff + ko + 8);
        CP_COMMIT();
    };

    stage(0, 0);
    if (NC > 1) stage(1, 1);

    int buf = 0;
    for (int c = 0; c < NC; ++c) {
        if (c + 1 < NC) CP_WAIT(1); else CP_WAIT(0);
        __syncthreads();
        if (c + 2 < NC) {
            int nb = buf + 2; if (nb >= NSTAGE) nb -= NSTAGE;
            stage(nb, c + 2);
        }

        const uint32_t cbase = sbase + buf * BUF_BYTES;
        #pragma unroll
        for (int ks = 0; ks < 2; ++ks) {
            const int ch = ks * 2 + lchunk;
            uint32_t bh[4][2], bl[4][2];
            #pragma unroll
            for (int h = 0; h < 2; ++h) {
                uint32_t r4[4];
                ldm_x4(r4, cbase + BHI + swz_off(wn * 32 + h * 16 + lrow, ch));
                bh[2*h][0] = r4[0]; bh[2*h+1][0] = r4[1];
                bh[2*h][1] = r4[2]; bh[2*h+1][1] = r4[3];
                ldm_x4(r4, cbase + BLO + swz_off(wn * 32 + h * 16 + lrow, ch));
                bl[2*h][0] = r4[0]; bl[2*h+1][0] = r4[1];
                bl[2*h][1] = r4[2]; bl[2*h+1][1] = r4[3];
            }
            #pragma unroll
            for (int mt = 0; mt < 4; ++mt) {
                uint32_t ah[4], al[4];
                ldm_x4(ah, cbase + AHI + swz_off(wm * 64 + mt * 16 + lrow, ch));
                ldm_x4(al, cbase + ALO + swz_off(wm * 64 + mt * 16 + lrow, ch));
                #pragma unroll
                for (int nt = 0; nt < 4; ++nt) {
                    mma_bf16(acc[mt][nt], ah, bh[nt]);
                    mma_bf16(acc[mt][nt], ah, bl[nt]);
                    mma_bf16(acc[mt][nt], al, bh[nt]);
                }
            }
        }
        if (++buf >= NSTAGE) buf = 0;
    }

    #pragma unroll
    for (int mt = 0; mt < 4; ++mt) {
        int row0 = wm * 64 + mt * 16 + g;
        #pragma unroll
        for (int nt = 0; nt < 4; ++nt) {
            int col = wn * 32 + nt * 8 + tg * 2;
            epi(row0,     col, acc[mt][nt][0], acc[mt][nt][1]);
            epi(row0 + 8, col, acc[mt][nt][2], acc[mt][nt][3]);
        }
    }
}

// ---------------- core 2: fp16 single-A x dual-B (2 MMAs per pair) ---------
// C = A * (Bh + Bl)^T  — exact except A's fp16 quantization.
template <class Epi>
__device__ __forceinline__ void gemm_core_sd(const fp16* __restrict__ A, int lda,
                                             const fp16* __restrict__ Bh,
                                             const fp16* __restrict__ Bl, int ldb,
                                             int K, Epi epi) {
    const int tid  = threadIdx.x;
    const int lane = tid & 31;
    const int wid  = tid >> 5;
    const int wm   = wid >> 2;
    const int wn   = wid & 3;
    const int g    = lane >> 2;
    const int tg   = lane & 3;
    const int lrow = lane & 15;
    const int lchunk = lane >> 4;
    const uint32_t sbase = smem_u32(dyn_smem);

    const int srow = tid >> 1;
    const int sh   = tid & 1;
    const uint32_t so0 = swz_off(srow, sh * 2);
    const uint32_t so1 = swz_off(srow, sh * 2 + 1);
    const size_t aoff = (size_t)srow * lda + sh * 16;
    const size_t boff = (size_t)srow * ldb + sh * 16;

    float acc[4][4][4];
    #pragma unroll
    for (int i = 0; i < 4; i++)
        #pragma unroll
        for (int j = 0; j < 4; j++)
            #pragma unroll
            for (int t = 0; t < 4; t++) acc[i][j][t] = 0.f;

    const int NC = K / TKC;

    auto stage = [&](int buf, int c) {
        uint32_t d = sbase + buf * SD_BUF;
        int ko = c * TKC;
        CP16(d + SD_AS + so0, A + aoff + ko);
        CP16(d + SD_AS + so1, A + aoff + ko + 8);
        CP16(d + SD_BH + so0, Bh + boff + ko);
        CP16(d + SD_BH + so1, Bh + boff + ko + 8);
        CP16(d + SD_BL + so0, Bl + boff + ko);
        CP16(d + SD_BL + so1, Bl + boff + ko + 8);
        CP_COMMIT();
    };

    stage(0, 0);
    if (NC > 1) stage(1, 1);

    int buf = 0;
    for (int c = 0; c < NC; ++c) {
        if (c + 1 < NC) CP_WAIT(1); else CP_WAIT(0);
        __syncthreads();
        if (c + 2 < NC) {
            int nb = buf + 2; if (nb >= NSTAGE) nb -= NSTAGE;
            stage(nb, c + 2);
        }

        const uint32_t cbase = sbase + buf * SD_BUF;
        #pragma unroll
        for (int ks = 0; ks < 2; ++ks) {
            const int ch = ks * 2 + lchunk;
            uint32_t bh[4][2], bl[4][2];
            #pragma unroll
            for (int h = 0; h < 2; ++h) {
                uint32_t r4[4];
                ldm_x4(r4, cbase + SD_BH + swz_off(wn * 32 + h * 16 + lrow, ch));
                bh[2*h][0] = r4[0]; bh[2*h+1][0] = r4[1];
                bh[2*h][1] = r4[2]; bh[2*h+1][1] = r4[3];
                ldm_x4(r4, cbase + SD_BL + swz_off(wn * 32 + h * 16 + lrow, ch));
                bl[2*h][0] = r4[0]; bl[2*h+1][0] = r4[1];
                bl[2*h][1] = r4[2]; bl[2*h+1][1] = r4[3];
            }
            #pragma unroll
            for (int mt = 0; mt < 4; ++mt) {
                uint32_t ah[4];
                ldm_x4(ah, cbase + SD_AS + swz_off(wm * 64 + mt * 16 + lrow, ch));
                #pragma unroll
                for (int nt = 0; nt < 4; ++nt) {
                    mma_fp16(acc[mt][nt], ah, bh[nt]);
                    mma_fp16(acc[mt][nt], ah, bl[nt]);
                }
            }
        }
        if (++buf >= NSTAGE) buf = 0;
    }

    #pragma unroll
    for (int mt = 0; mt < 4; ++mt) {
        int row0 = wm * 64 + mt * 16 + g;
        #pragma unroll
        for (int nt = 0; nt < 4; ++nt) {
            int col = wn * 32 + nt * 8 + tg * 2;
            epi(row0,     col, acc[mt][nt][0], acc[mt][nt][1]);
            epi(row0 + 8, col, acc[mt][nt][2], acc[mt][nt][3]);
        }
    }
}

// ---------------- GEMM kernels ---------------------------------------------
struct EpiUV {
    const float* buv; int bm, bn;
    __device__ __forceinline__ void operator()(int r, int c, float a, float b) const {
        float va = a + buv[bn + c];
        float vb = b + buv[bn + c + 1];
        float* p = g_uv + (size_t)(bm + r) * UVC + bn + c;
        p[0] = va / (1.0f + __expf(-va));
        p[1] = vb / (1.0f + __expf(-vb));
    }
};
__global__ __launch_bounds__(256, 2) void k_gemm_uv(const float* __restrict__ buv) {
    const int bm = blockIdx.y * TM, bn = blockIdx.x * TN;
    gemm_core(g_xs_hi + (size_t)bm * HIDDEN, g_xs_lo + (size_t)bm * HIDDEN, HIDDEN,
              g_WuvT_hi + (size_t)bn * HIDDEN, g_WuvT_lo + (size_t)bn * HIDDEN, HIDDEN,
              HIDDEN, EpiUV{buv, bm, bn});
}

struct EpiScores {
    int b, bm, bn;
    __device__ __forceinline__ void operator()(int r, int c, float a, float bb) const {
        float wa = fmaxf(a  * 0.08838834764831845f, 0.f);
        float wb = fmaxf(bb * 0.08838834764831845f, 0.f);
        size_t off = (size_t)b * NSEQ * NSEQ + (size_t)(bm + r) * NSEQ + bn + c;
        *(uint32_t*)(g_s_h + off) = pack_h2(wa * wa, wb * wb);
    }
};
__global__ __launch_bounds__(256, 2) void k_gemm_scores() {
    const int b = blockIdx.z;
    const int bm = blockIdx.y * TM, bn = blockIdx.x * TN;
    size_t qa = (size_t)(b * NSEQ + bm) * S_DIM;
    size_t kb = (size_t)(b * NSEQ + bn) * S_DIM;
    gemm_core(g_q_hi + qa, g_q_lo + qa, S_DIM,
              g_k_hi + kb, g_k_lo + kb, S_DIM, S_DIM,
              EpiScores{b, bm, bn});
}

struct EpiAttn {
    int b, bm, bn;
    __device__ __forceinline__ void operator()(int r, int c, float a, float bvv) const {
        size_t tok = (size_t)b * NSEQ + bm + r;
        const float* u = g_uv + tok * UVC + bn + c;
        *(uint32_t*)(g_attn_h + tok * E_DIM + bn + c) = pack_h2(a * u[0], bvv * u[1]);
    }
};
__global__ __launch_bounds__(256, 2) void k_gemm_attn() {
    const int b = blockIdx.z;
    const int bm = blockIdx.y * TM, bn = blockIdx.x * TN;
    size_t sa = (size_t)b * NSEQ * NSEQ + (size_t)bm * NSEQ;
    size_t vb = (size_t)b * E_DIM * NSEQ + (size_t)bn * NSEQ;
    gemm_core_sd(g_s_h + sa, NSEQ,
                 g_vT_h + vb, g_vT_l + vb, NSEQ, NSEQ,
                 EpiAttn{b, bm, bn});
}

struct EpiOut {
    const float* x; const float* bo; float* out; int bm, bn;
    __device__ __forceinline__ void operator()(int r, int c, float a, float b) const {
        size_t row = bm + r;
        int col = bn + c;
        out[row * HIDDEN + col]     = a + bo[col]     + x[row * HIDDEN + col];
        out[row * HIDDEN + col + 1] = b + bo[col + 1] + x[row * HIDDEN + col + 1];
    }
};
__global__ __launch_bounds__(256, 2) void k_gemm_out(const float* __restrict__ x,
                                                     const float* __restrict__ bo,
                                                     float* __restrict__ out) {
    const int bm = blockIdx.y * TM, bn = blockIdx.x * TN;
    gemm_core_sd(g_attn_h + (size_t)bm * E_DIM, E_DIM,
                 g_WoT_h + (size_t)bn * E_DIM, g_WoT_l + (size_t)bn * E_DIM, E_DIM,
                 E_DIM, EpiOut{x, bo, out, bm, bn});
}

// ---------------- transposes -----------------------------------------------
__global__ void k_transpose_wuv(const float* __restrict__ Wuv) {
    __shared__ float t[32][33];
    int c0 = blockIdx.x * 32, r0 = blockIdx.y * 32;
    int tx = threadIdx.x, ty = threadIdx.y;
    #pragma unroll
    for (int j = 0; j < 32; j += 8)
        t[ty + j][tx] = Wuv[(size_t)(r0 + ty + j) * UVC + c0 + tx];
    __syncthreads();
    #pragma unroll
    for (int j = 0; j < 32; j += 8) {
        bf16 h, l;
        split1(t[tx][ty + j], h, l);
        size_t off = (size_t)(c0 + ty + j) * HIDDEN + r0 + tx;
        g_WuvT_hi[off] = h;
        g_WuvT_lo[off] = l;
    }
}
__global__ void k_transpose_wo(const float* __restrict__ Wo) {
    __shared__ float t[32][33];
    int c0 = blockIdx.x * 32, r0 = blockIdx.y * 32;
    int tx = threadIdx.x, ty = threadIdx.y;
    #pragma unroll
    for (int j = 0; j < 32; j += 8)
        t[ty + j][tx] = Wo[(size_t)(r0 + ty + j) * HIDDEN + c0 + tx];
    __syncthreads();
    #pragma unroll
    for (int j = 0; j < 32; j += 8) {
        fp16 h, l;
        split1h(t[tx][ty + j], h, l);
        size_t off = (size_t)(c0 + ty + j) * E_DIM + r0 + tx;
        g_WoT_h[off] = h;
        g_WoT_l[off] = l;
    }
}
__global__ void k_transpose_v() {
    __shared__ float t[32][33];
    int b = blockIdx.z;
    const float* src = g_uv + (size_t)b * NSEQ * UVC + E_DIM;
    fp16* dh = g_vT_h + (size_t)b * E_DIM * NSEQ;
    fp16* dl = g_vT_l + (size_t)b * E_DIM * NSEQ;
    int c0 = blockIdx.x * 32, r0 = blockIdx.y * 32;
    int tx = threadIdx.x, ty = threadIdx.y;
    #pragma unroll
    for (int j = 0; j < 32; j += 8)
        t[ty + j][tx] = src[(size_t)(r0 + ty + j) * UVC + c0 + tx];
    __syncthreads();
    #pragma unroll
    for (int j = 0; j < 32; j += 8) {
        fp16 h, l;
        split1h(t[tx][ty + j], h, l);
        size_t off = (size_t)(c0 + ty + j) * NSEQ + r0 + tx;
        dh[off] = h;
        dl[off] = l;
    }
}

// ---------------- small kernels --------------------------------------------
__global__ void trig_kernel() {
    int t = blockIdx.x * blockDim.x + threadIdx.x;
    if (t >= NSEQ * HALF) return;
    int pos = t >> 6;
    int j = t & 63;
    double freq_d = pow(10000.0, (double)j / 64.0);
    float freq_f = (float)freq_d;
    float arg = __fmul_rn((float)pos, freq_f);
    double a = (double)arg;
    g_sinT[t] = (float)sin(a);
    g_cosT[t] = (float)cos(a);
}

__global__ void scale_kernel(const float* __restrict__ x, const float* __restrict__ g) {
    int m = blockIdx.x;
    const float* xr = x + (size_t)m * HIDDEN;
    float ss = 0.f;
    for (int i = threadIdx.x; i < HIDDEN; i += 256) {
        float v = xr[i];
        ss = fmaf(v, v, ss);
    }
    #pragma unroll
    for (int o = 16; o; o >>= 1) ss += __shfl_xor_sync(0xffffffffu, ss, o);
    __shared__ float red[8];
    __shared__ float s_sh;
    if ((threadIdx.x & 31) == 0) red[threadIdx.x >> 5] = ss;
    __syncthreads();
    if (threadIdx.x == 0) {
        float t = 0.f;
        #pragma unroll
        for (int i = 0; i < 8; i++) t += red[i];
        float norm = sqrtf(t) * 0.04419417382415922f;
        s_sh = g[0] / fmaxf(norm, 1e-5f);
    }
    __syncthreads();
    float s = s_sh;
    int i2 = threadIdx.x * 2;
    float2 v = *(const float2*)(xr + i2);
    uint32_t hi, lo;
    split2(v.x * s, v.y * s, hi, lo);
    *(uint32_t*)(g_xs_hi + (size_t)m * HIDDEN + i2) = hi;
    *(uint32_t*)(g_xs_lo + (size_t)m * HIDDEN + i2) = lo;
}

__global__ void rope_kernel(const float* __restrict__ gamma, const float* __restrict__ beta) {
    int m = blockIdx.x;
    int j = threadIdx.x;
    int pos = m & (NSEQ - 1);
    const float* base = g_uv + (size_t)m * UVC + 2 * E_DIM;
    float b1 = base[j];
    float b2 = base[j + HALF];
    float c = g_cosT[pos * HALF + j];
    float sn = g_sinT[pos * HALF + j];
    float q1 = b1 * gamma[j] + beta[j];
    float q2 = b2 * gamma[j + HALF] + beta[j + HALF];
    float k1 = b1 * gamma[S_DIM + j] + beta[S_DIM + j];
    float k2 = b2 * gamma[S_DIM + j + HALF] + beta[S_DIM + j + HALF];
    float qa = q1 * c - q2 * sn, qb = q2 * c + q1 * sn;
    float ka = k1 * c - k2 * sn, kb = k2 * c + k1 * sn;
    bf16 h, l;
    int o = m * S_DIM + j;
    split1(qa, h, l); g_q_hi[o] = h;        g_q_lo[o] = l;
    split1(qb, h, l); g_q_hi[o + HALF] = h; g_q_lo[o + HALF] = l;
    split1(ka, h, l); g_k_hi[o] = h;        g_k_lo[o] = l;
    split1(kb, h, l); g_k_hi[o + HALF] = h; g_k_lo[o + HALF] = l;
}

// ---------------- launcher -------------------------------------------------
extern "C" void kernel_launch(void* const* d_in, const int* in_sizes, int n_in,
                              void* d_out, int out_size) {
    const float* x     = (const float*)d_in[0];
    const float* Wuv   = (const float*)d_in[1];
    const float* buv   = (const float*)d_in[2];
    const float* gamma = (const float*)d_in[3];
    const float* beta  = (const float*)d_in[4];
    const float* Wo    = (const float*)d_in[5];
    const float* bo    = (const float*)d_in[6];
    const float* g     = (const float*)d_in[7];
    float* out = (float*)d_out;

    cudaFuncSetAttribute(k_gemm_uv,     cudaFuncAttributeMaxDynamicSharedMemorySize, SMEM_TOTAL);
    cudaFuncSetAttribute(k_gemm_scores, cudaFuncAttributeMaxDynamicSharedMemorySize, SMEM_TOTAL);
    cudaFuncSetAttribute(k_gemm_attn,   cudaFuncAttributeMaxDynamicSharedMemorySize, SD_SMEM);
    cudaFuncSetAttribute(k_gemm_out,    cudaFuncAttributeMaxDynamicSharedMemorySize, SD_SMEM);

    trig_kernel<<<(NSEQ * HALF + 255) / 256, 256>>>();
    scale_kernel<<<BTOK, 256>>>(x, g);
    k_transpose_wuv<<<dim3(UVC / 32, HIDDEN / 32), dim3(32, 8)>>>(Wuv);
    k_transpose_wo<<<dim3(HIDDEN / 32, E_DIM / 32), dim3(32, 8)>>>(Wo);
    k_gemm_uv<<<dim3(UVC / TN, BTOK / TM), 256, SMEM_TOTAL>>>(buv);
    k_transpose_v<<<dim3(E_DIM / 32, NSEQ / 32, NB), dim3(32, 8)>>>();
    rope_kernel<<<BTOK, HALF>>>(gamma, beta);
    k_gemm_scores<<<dim3(NSEQ / TN, NSEQ / TM, NB), 256, SMEM_TOTAL>>>();
    k_gemm_attn<<<dim3(E_DIM / TN, NSEQ / TM, NB), 256, SD_SMEM>>>();
    k_gemm_out<<<dim3(HIDDEN / TN, BTOK / TM), 256, SD_SMEM>>>(x, bo, out);
}

// round 15
// speedup vs baseline: 1.0020x; 1.0020x over previous
#include <cuda_runtime.h>
#include <cuda_bf16.h>
#include <cuda_fp16.h>
#include <cstdint>
#include <math.h>

#define HIDDEN 512
#define E_DIM  1024
#define S_DIM  128
#define NB     32
#define NSEQ   1024
#define BTOK   (NB * NSEQ)
#define UVC    (2 * E_DIM + S_DIM)   // 2176
#define HALF   64

#define TM 128
#define TN 128
#define TKC 32                        // K elements per chunk (2B each)
#define RSTR 64                       // smem row stride (bytes, swizzled)
// bf16 3-term core regions
#define AHI 0
#define ALO 8192
#define BHI 16384
#define BLO 24576
#define BUF_BYTES 32768
#define NSTAGE 3
#define SMEM_TOTAL (NSTAGE * BUF_BYTES)     // 98304
// fp16 single-A dual-B core regions
#define SD_AS  0
#define SD_BH  8192
#define SD_BL  16384
#define SD_BUF 24576
#define SD_SMEM (NSTAGE * SD_BUF)           // 73728

typedef __nv_bfloat16 bf16;
typedef __half        fp16;

// ---------------- scratch (device globals) ---------------------------------
__device__ float g_uv[(size_t)BTOK * UVC];
__device__ bf16  g_xs_hi[(size_t)BTOK * HIDDEN];
__device__ bf16  g_xs_lo[(size_t)BTOK * HIDDEN];
__device__ bf16  g_WuvT_hi[(size_t)UVC * HIDDEN];
__device__ bf16  g_WuvT_lo[(size_t)UVC * HIDDEN];
__device__ fp16  g_WoT_h[(size_t)HIDDEN * E_DIM];
__device__ fp16  g_WoT_l[(size_t)HIDDEN * E_DIM];
__device__ bf16  g_q_hi[BTOK * S_DIM];
__device__ bf16  g_q_lo[BTOK * S_DIM];
__device__ bf16  g_k_hi[BTOK * S_DIM];
__device__ bf16  g_k_lo[BTOK * S_DIM];
__device__ fp16  g_s_h[(size_t)NB * NSEQ * NSEQ];     // scores, single fp16
__device__ fp16  g_vT_h[(size_t)NB * E_DIM * NSEQ];
__device__ fp16  g_vT_l[(size_t)NB * E_DIM * NSEQ];
__device__ fp16  g_attn_h[(size_t)BTOK * E_DIM];      // attn, single fp16
__device__ float g_sinT[NSEQ * HALF];
__device__ float g_cosT[NSEQ * HALF];

extern __shared__ char dyn_smem[];

// ---------------- PTX helpers ----------------------------------------------
__device__ __forceinline__ uint32_t smem_u32(const void* p) {
    uint32_t a;
    asm("{ .reg .u64 t; cvta.to.shared.u64 t, %1; cvt.u32.u64 %0, t; }"
        : "=r"(a) : "l"(p));
    return a;
}
__device__ __forceinline__ void ldm_x4(uint32_t* r, uint32_t addr) {
    asm volatile("ldmatrix.sync.aligned.m8n8.x4.shared.b16 {%0,%1,%2,%3}, [%4];"
        : "=r"(r[0]), "=r"(r[1]), "=r"(r[2]), "=r"(r[3]) : "r"(addr));
}
__device__ __forceinline__ void mma_bf16(float* d, const uint32_t* a, const uint32_t* b) {
    asm volatile(
        "mma.sync.aligned.m16n8k16.row.col.f32.bf16.bf16.f32 "
        "{%0,%1,%2,%3}, {%4,%5,%6,%7}, {%8,%9}, {%0,%1,%2,%3};"
        : "+f"(d[0]), "+f"(d[1]), "+f"(d[2]), "+f"(d[3])
        : "r"(a[0]), "r"(a[1]), "r"(a[2]), "r"(a[3]), "r"(b[0]), "r"(b[1]));
}
__device__ __forceinline__ void mma_fp16(float* d, const uint32_t* a, const uint32_t* b) {
    asm volatile(
        "mma.sync.aligned.m16n8k16.row.col.f32.f16.f16.f32 "
        "{%0,%1,%2,%3}, {%4,%5,%6,%7}, {%8,%9}, {%0,%1,%2,%3};"
        : "+f"(d[0]), "+f"(d[1]), "+f"(d[2]), "+f"(d[3])
        : "r"(a[0]), "r"(a[1]), "r"(a[2]), "r"(a[3]), "r"(b[0]), "r"(b[1]));
}
#define CP16(dst, src) \
    asm volatile("cp.async.cg.shared.global [%0], [%1], 16;" :: "r"(dst), "l"(src))
#define CP_COMMIT() asm volatile("cp.async.commit_group;" ::: "memory")
#define CP_WAIT(n)  asm volatile("cp.async.wait_group %0;" :: "n"(n) : "memory")

// swizzle: row r, 16B-chunk j -> byte offset within region
__device__ __forceinline__ uint32_t swz_off(int row, int chunk) {
    return (uint32_t)(row * RSTR) + (uint32_t)((chunk ^ ((row >> 1) & 3)) << 4);
}

// fp32 -> bf16 hi/lo
__device__ __forceinline__ void split1(float v, bf16& h, bf16& l) {
    h = __float2bfloat16(v);
    l = __float2bfloat16(v - __bfloat162float(h));
}
__device__ __forceinline__ void split2(float a, float b, uint32_t& hi, uint32_t& lo) {
    bf16 h0, l0, h1, l1;
    split1(a, h0, l0);
    split1(b, h1, l1);
    hi = ((uint32_t)__bfloat16_as_ushort(h1) << 16) | __bfloat16_as_ushort(h0);
    lo = ((uint32_t)__bfloat16_as_ushort(l1) << 16) | __bfloat16_as_ushort(l0);
}
// fp32 -> fp16 hi/lo
__device__ __forceinline__ void split1h(float v, fp16& h, fp16& l) {
    h = __float2half(v);
    l = __float2half(v - __half2float(h));
}
__device__ __forceinline__ uint32_t pack_h2(float a, float b) {
    __half2 p = __floats2half2_rn(a, b);
    return *(uint32_t*)&p;
}

// ---------------- core 1: bf16 3-term (A,B both hi/lo) ---------------------
template <class Epi>
__device__ __forceinline__ void gemm_core(const bf16* __restrict__ Ahi,
                                          const bf16* __restrict__ Alo, int lda,
                                          const bf16* __restrict__ Bhi,
                                          const bf16* __restrict__ Blo, int ldb,
                                          int K, Epi epi) {
    const int tid  = threadIdx.x;
    const int lane = tid & 31;
    const int wid  = tid >> 5;
    const int wm   = wid >> 2;
    const int wn   = wid & 3;
    const int g    = lane >> 2;
    const int tg   = lane & 3;
    const int lrow = lane & 15;
    const int lchunk = lane >> 4;
    const uint32_t sbase = smem_u32(dyn_smem);

    const int srow = tid >> 1;
    const int sh   = tid & 1;
    const uint32_t so0 = swz_off(srow, sh * 2);
    const uint32_t so1 = swz_off(srow, sh * 2 + 1);
    const size_t aoff = (size_t)srow * lda + sh * 16;
    const size_t boff = (size_t)srow * ldb + sh * 16;

    float acc[4][4][4];
    #pragma unroll
    for (int i = 0; i < 4; i++)
        #pragma unroll
        for (int j = 0; j < 4; j++)
            #pragma unroll
            for (int t = 0; t < 4; t++) acc[i][j][t] = 0.f;

    const int NC = K / TKC;

    auto stage = [&](int buf, int c) {
        uint32_t d = sbase + buf * BUF_BYTES;
        int ko = c * TKC;
        CP16(d + AHI + so0, Ahi + aoff + ko);
        CP16(d + AHI + so1, Ahi + aoff + ko + 8);
        CP16(d + ALO + so0, Alo + aoff + ko);
        CP16(d + ALO + so1, Alo + aoff + ko + 8);
        CP16(d + BHI + so0, Bhi + boff + ko);
        CP16(d + BHI + so1, Bhi + boff + ko + 8);
        CP16(d + BLO + so0, Blo + boff + ko);
        CP16(d + BLO + so1, Blo + boff + ko + 8);
        CP_COMMIT();
    };

    stage(0, 0);
    if (NC > 1) stage(1, 1);

    int buf = 0;
    for (int c = 0; c < NC; ++c) {
        if (c + 1 < NC) CP_WAIT(1); else CP_WAIT(0);
        __syncthreads();
        if (c + 2 < NC) {
            int nb = buf + 2; if (nb >= NSTAGE) nb -= NSTAGE;
            stage(nb, c + 2);
        }

        const uint32_t cbase = sbase + buf * BUF_BYTES;
        #pragma unroll
        for (int ks = 0; ks < 2; ++ks) {
            const int ch = ks * 2 + lchunk;
            uint32_t bh[4][2], bl[4][2];
            #pragma unroll
            for (int h = 0; h < 2; ++h) {
                uint32_t r4[4];
                ldm_x4(r4, cbase + BHI + swz_off(wn * 32 + h * 16 + lrow, ch));
                bh[2*h][0] = r4[0]; bh[2*h+1][0] = r4[1];
                bh[2*h][1] = r4[2]; bh[2*h+1][1] = r4[3];
                ldm_x4(r4, cbase + BLO + swz_off(wn * 32 + h * 16 + lrow, ch));
                bl[2*h][0] = r4[0]; bl[2*h+1][0] = r4[1];
                bl[2*h][1] = r4[2]; bl[2*h+1][1] = r4[3];
            }
            #pragma unroll
            for (int mt = 0; mt < 4; ++mt) {
                uint32_t ah[4], al[4];
                ldm_x4(ah, cbase + AHI + swz_off(wm * 64 + mt * 16 + lrow, ch));
                ldm_x4(al, cbase + ALO + swz_off(wm * 64 + mt * 16 + lrow, ch));
                #pragma unroll
                for (int nt = 0; nt < 4; ++nt) {
                    mma_bf16(acc[mt][nt], ah, bh[nt]);
                    mma_bf16(acc[mt][nt], ah, bl[nt]);
                    mma_bf16(acc[mt][nt], al, bh[nt]);
                }
            }
        }
        if (++buf >= NSTAGE) buf = 0;
    }

    #pragma unroll
    for (int mt = 0; mt < 4; ++mt) {
        int row0 = wm * 64 + mt * 16 + g;
        #pragma unroll
        for (int nt = 0; nt < 4; ++nt) {
            int col = wn * 32 + nt * 8 + tg * 2;
            epi(row0,     col, acc[mt][nt][0], acc[mt][nt][1]);
            epi(row0 + 8, col, acc[mt][nt][2], acc[mt][nt][3]);
        }
    }
}

// ---------------- core 2: fp16 single-A x dual-B (2 MMAs per pair) ---------
// C = A * (Bh + Bl)^T  — exact except A's fp16 quantization.
template <class Epi>
__device__ __forceinline__ void gemm_core_sd(const fp16* __restrict__ A, int lda,
                                             const fp16* __restrict__ Bh,
                                             const fp16* __restrict__ Bl, int ldb,
                                             int K, Epi epi) {
    const int tid  = threadIdx.x;
    const int lane = tid & 31;
    const int wid  = tid >> 5;
    const int wm   = wid >> 2;
    const int wn   = wid & 3;
    const int g    = lane >> 2;
    const int tg   = lane & 3;
    const int lrow = lane & 15;
    const int lchunk = lane >> 4;
    const uint32_t sbase = smem_u32(dyn_smem);

    const int srow = tid >> 1;
    const int sh   = tid & 1;
    const uint32_t so0 = swz_off(srow, sh * 2);
    const uint32_t so1 = swz_off(srow, sh * 2 + 1);
    const size_t aoff = (size_t)srow * lda + sh * 16;
    const size_t boff = (size_t)srow * ldb + sh * 16;

    float acc[4][4][4];
    #pragma unroll
    for (int i = 0; i < 4; i++)
        #pragma unroll
        for (int j = 0; j < 4; j++)
            #pragma unroll
            for (int t = 0; t < 4; t++) acc[i][j][t] = 0.f;

    const int NC = K / TKC;

    auto stage = [&](int buf, int c) {
        uint32_t d = sbase + buf * SD_BUF;
        int ko = c * TKC;
        CP16(d + SD_AS + so0, A + aoff + ko);
        CP16(d + SD_AS + so1, A + aoff + ko + 8);
        CP16(d + SD_BH + so0, Bh + boff + ko);
        CP16(d + SD_BH + so1, Bh + boff + ko + 8);
        CP16(d + SD_BL + so0, Bl + boff + ko);
        CP16(d + SD_BL + so1, Bl + boff + ko + 8);
        CP_COMMIT();
    };

    stage(0, 0);
    if (NC > 1) stage(1, 1);

    int buf = 0;
    for (int c = 0; c < NC; ++c) {
        if (c + 1 < NC) CP_WAIT(1); else CP_WAIT(0);
        __syncthreads();
        if (c + 2 < NC) {
            int nb = buf + 2; if (nb >= NSTAGE) nb -= NSTAGE;
            stage(nb, c + 2);
        }

        const uint32_t cbase = sbase + buf * SD_BUF;
        #pragma unroll
        for (int ks = 0; ks < 2; ++ks) {
            const int ch = ks * 2 + lchunk;
            uint32_t bh[4][2], bl[4][2];
            #pragma unroll
            for (int h = 0; h < 2; ++h) {
                uint32_t r4[4];
                ldm_x4(r4, cbase + SD_BH + swz_off(wn * 32 + h * 16 + lrow, ch));
                bh[2*h][0] = r4[0]; bh[2*h+1][0] = r4[1];
                bh[2*h][1] = r4[2]; bh[2*h+1][1] = r4[3];
                ldm_x4(r4, cbase + SD_BL + swz_off(wn * 32 + h * 16 + lrow, ch));
                bl[2*h][0] = r4[0]; bl[2*h+1][0] = r4[1];
                bl[2*h][1] = r4[2]; bl[2*h+1][1] = r4[3];
            }
            #pragma unroll
            for (int mt = 0; mt < 4; ++mt) {
                uint32_t ah[4];
                ldm_x4(ah, cbase + SD_AS + swz_off(wm * 64 + mt * 16 + lrow, ch));
                #pragma unroll
                for (int nt = 0; nt < 4; ++nt) {
                    mma_fp16(acc[mt][nt], ah, bh[nt]);
                    mma_fp16(acc[mt][nt], ah, bl[nt]);
                }
            }
        }
        if (++buf >= NSTAGE) buf = 0;
    }

    #pragma unroll
    for (int mt = 0; mt < 4; ++mt) {
        int row0 = wm * 64 + mt * 16 + g;
        #pragma unroll
        for (int nt = 0; nt < 4; ++nt) {
            int col = wn * 32 + nt * 8 + tg * 2;
            epi(row0,     col, acc[mt][nt][0], acc[mt][nt][1]);
            epi(row0 + 8, col, acc[mt][nt][2], acc[mt][nt][3]);
        }
    }
}

// ---------------- GEMM kernels ---------------------------------------------
struct EpiUV {
    const float* buv; int bm, bn;
    __device__ __forceinline__ void operator()(int r, int c, float a, float b) const {
        float va = a + buv[bn + c];
        float vb = b + buv[bn + c + 1];
        float* p = g_uv + (size_t)(bm + r) * UVC + bn + c;
        p[0] = va / (1.0f + __expf(-va));
        p[1] = vb / (1.0f + __expf(-vb));
    }
};
__global__ __launch_bounds__(256, 2) void k_gemm_uv(const float* __restrict__ buv) {
    const int bm = blockIdx.y * TM, bn = blockIdx.x * TN;
    gemm_core(g_xs_hi + (size_t)bm * HIDDEN, g_xs_lo + (size_t)bm * HIDDEN, HIDDEN,
              g_WuvT_hi + (size_t)bn * HIDDEN, g_WuvT_lo + (size_t)bn * HIDDEN, HIDDEN,
              HIDDEN, EpiUV{buv, bm, bn});
}

struct EpiScores {
    int b, bm, bn;
    __device__ __forceinline__ void operator()(int r, int c, float a, float bb) const {
        float wa = fmaxf(a  * 0.08838834764831845f, 0.f);
        float wb = fmaxf(bb * 0.08838834764831845f, 0.f);
        size_t off = (size_t)b * NSEQ * NSEQ + (size_t)(bm + r) * NSEQ + bn + c;
        *(uint32_t*)(g_s_h + off) = pack_h2(wa * wa, wb * wb);
    }
};
__global__ __launch_bounds__(256, 2) void k_gemm_scores() {
    const int b = blockIdx.z;
    const int bm = blockIdx.y * TM, bn = blockIdx.x * TN;
    size_t qa = (size_t)(b * NSEQ + bm) * S_DIM;
    size_t kb = (size_t)(b * NSEQ + bn) * S_DIM;
    gemm_core(g_q_hi + qa, g_q_lo + qa, S_DIM,
              g_k_hi + kb, g_k_lo + kb, S_DIM, S_DIM,
              EpiScores{b, bm, bn});
}

struct EpiAttn {
    int b, bm, bn;
    __device__ __forceinline__ void operator()(int r, int c, float a, float bvv) const {
        size_t tok = (size_t)b * NSEQ + bm + r;
        const float* u = g_uv + tok * UVC + bn + c;
        *(uint32_t*)(g_attn_h + tok * E_DIM + bn + c) = pack_h2(a * u[0], bvv * u[1]);
    }
};
__global__ __launch_bounds__(256, 2) void k_gemm_attn() {
    const int b = blockIdx.z;
    const int bm = blockIdx.y * TM, bn = blockIdx.x * TN;
    size_t sa = (size_t)b * NSEQ * NSEQ + (size_t)bm * NSEQ;
    size_t vb = (size_t)b * E_DIM * NSEQ + (size_t)bn * NSEQ;
    gemm_core_sd(g_s_h + sa, NSEQ,
                 g_vT_h + vb, g_vT_l + vb, NSEQ, NSEQ,
                 EpiAttn{b, bm, bn});
}

struct EpiOut {
    const float* x; const float* bo; float* out; int bm, bn;
    __device__ __forceinline__ void operator()(int r, int c, float a, float b) const {
        size_t row = bm + r;
        int col = bn + c;
        out[row * HIDDEN + col]     = a + bo[col]     + x[row * HIDDEN + col];
        out[row * HIDDEN + col + 1] = b + bo[col + 1] + x[row * HIDDEN + col + 1];
    }
};
__global__ __launch_bounds__(256, 2) void k_gemm_out(const float* __restrict__ x,
                                                     const float* __restrict__ bo,
                                                     float* __restrict__ out) {
    const int bm = blockIdx.y * TM, bn = blockIdx.x * TN;
    gemm_core_sd(g_attn_h + (size_t)bm * E_DIM, E_DIM,
                 g_WoT_h + (size_t)bn * E_DIM, g_WoT_l + (size_t)bn * E_DIM, E_DIM,
                 E_DIM, EpiOut{x, bo, out, bm, bn});
}

// ---------------- transposes -----------------------------------------------
__global__ void k_transpose_wuv(const float* __restrict__ Wuv) {
    __shared__ float t[32][33];
    int c0 = blockIdx.x * 32, r0 = blockIdx.y * 32;
    int tx = threadIdx.x, ty = threadIdx.y;
    #pragma unroll
    for (int j = 0; j < 32; j += 8)
        t[ty + j][tx] = Wuv[(size_t)(r0 + ty + j) * UVC + c0 + tx];
    __syncthreads();
    #pragma unroll
    for (int j = 0; j < 32; j += 8) {
        bf16 h, l;
        split1(t[tx][ty + j], h, l);
        size_t off = (size_t)(c0 + ty + j) * HIDDEN + r0 + tx;
        g_WuvT_hi[off] = h;
        g_WuvT_lo[off] = l;
    }
}
__global__ void k_transpose_wo(const float* __restrict__ Wo) {
    __shared__ float t[32][33];
    int c0 = blockIdx.x * 32, r0 = blockIdx.y * 32;
    int tx = threadIdx.x, ty = threadIdx.y;
    #pragma unroll
    for (int j = 0; j < 32; j += 8)
        t[ty + j][tx] = Wo[(size_t)(r0 + ty + j) * HIDDEN + c0 + tx];
    __syncthreads();
    #pragma unroll
    for (int j = 0; j < 32; j += 8) {
        fp16 h, l;
        split1h(t[tx][ty + j], h, l);
        size_t off = (size_t)(c0 + ty + j) * E_DIM + r0 + tx;
        g_WoT_h[off] = h;
        g_WoT_l[off] = l;
    }
}
__global__ void k_transpose_v() {
    __shared__ float t[32][33];
    int b = blockIdx.z;
    const float* src = g_uv + (size_t)b * NSEQ * UVC + E_DIM;
    fp16* dh = g_vT_h + (size_t)b * E_DIM * NSEQ;
    fp16* dl = g_vT_l + (size_t)b * E_DIM * NSEQ;
    int c0 = blockIdx.x * 32, r0 = blockIdx.y * 32;
    int tx = threadIdx.x, ty = threadIdx.y;
    #pragma unroll
    for (int j = 0; j < 32; j += 8)
        t[ty + j][tx] = src[(size_t)(r0 + ty + j) * UVC + c0 + tx];
    __syncthreads();
    #pragma unroll
    for (int j = 0; j < 32; j += 8) {
        fp16 h, l;
        split1h(t[tx][ty + j], h, l);
        size_t off = (size_t)(c0 + ty + j) * NSEQ + r0 + tx;
        dh[off] = h;
        dl[off] = l;
    }
}

// ---------------- small kernels --------------------------------------------
__global__ void trig_kernel() {
    int t = blockIdx.x * blockDim.x + threadIdx.x;
    if (t >= NSEQ * HALF) return;
    int pos = t >> 6;
    int j = t & 63;
    double freq_d = pow(10000.0, (double)j / 64.0);
    float freq_f = (float)freq_d;
    float arg = __fmul_rn((float)pos, freq_f);
    double a = (double)arg;
    g_sinT[t] = (float)sin(a);
    g_cosT[t] = (float)cos(a);
}

__global__ void scale_kernel(const float* __restrict__ x, const float* __restrict__ g) {
    int m = blockIdx.x;
    const float* xr = x + (size_t)m * HIDDEN;
    float ss = 0.f;
    for (int i = threadIdx.x; i < HIDDEN; i += 256) {
        float v = xr[i];
        ss = fmaf(v, v, ss);
    }
    #pragma unroll
    for (int o = 16; o; o >>= 1) ss += __shfl_xor_sync(0xffffffffu, ss, o);
    __shared__ float red[8];
    __shared__ float s_sh;
    if ((threadIdx.x & 31) == 0) red[threadIdx.x >> 5] = ss;
    __syncthreads();
    if (threadIdx.x == 0) {
        float t = 0.f;
        #pragma unroll
        for (int i = 0; i < 8; i++) t += red[i];
        float norm = sqrtf(t) * 0.04419417382415922f;
        s_sh = g[0] / fmaxf(norm, 1e-5f);
    }
    __syncthreads();
    float s = s_sh;
    int i2 = threadIdx.x * 2;
    float2 v = *(const float2*)(xr + i2);
    uint32_t hi, lo;
    split2(v.x * s, v.y * s, hi, lo);
    *(uint32_t*)(g_xs_hi + (size_t)m * HIDDEN + i2) = hi;
    *(uint32_t*)(g_xs_lo + (size_t)m * HIDDEN + i2) = lo;
}

__global__ void rope_kernel(const float* __restrict__ gamma, const float* __restrict__ beta) {
    int m = blockIdx.x;
    int j = threadIdx.x;
    int pos = m & (NSEQ - 1);
    const float* base = g_uv + (size_t)m * UVC + 2 * E_DIM;
    float b1 = base[j];
    float b2 = base[j + HALF];
    float c = g_cosT[pos * HALF + j];
    float sn = g_sinT[pos * HALF + j];
    float q1 = b1 * gamma[j] + beta[j];
    float q2 = b2 * gamma[j + HALF] + beta[j + HALF];
    float k1 = b1 * gamma[S_DIM + j] + beta[S_DIM + j];
    float k2 = b2 * gamma[S_DIM + j + HALF] + beta[S_DIM + j + HALF];
    float qa = q1 * c - q2 * sn, qb = q2 * c + q1 * sn;
    float ka = k1 * c - k2 * sn, kb = k2 * c + k1 * sn;
    bf16 h, l;
    int o = m * S_DIM + j;
    split1(qa, h, l); g_q_hi[o] = h;        g_q_lo[o] = l;
    split1(qb, h, l); g_q_hi[o + HALF] = h; g_q_lo[o + HALF] = l;
    split1(ka, h, l); g_k_hi[o] = h;        g_k_lo[o] = l;
    split1(kb, h, l); g_k_hi[o + HALF] = h; g_k_lo[o + HALF] = l;
}

// ---------------- launcher -------------------------------------------------
extern "C" void kernel_launch(void* const* d_in, const int* in_sizes, int n_in,
                              void* d_out, int out_size) {
    const float* x     = (const float*)d_in[0];
    const float* Wuv   = (const float*)d_in[1];
    const float* buv   = (const float*)d_in[2];
    const float* gamma = (const float*)d_in[3];
    const float* beta  = (const float*)d_in[4];
    const float* Wo    = (const float*)d_in[5];
    const float* bo    = (const float*)d_in[6];
    const float* g     = (const float*)d_in[7];
    float* out = (float*)d_out;

    cudaFuncSetAttribute(k_gemm_uv,     cudaFuncAttributeMaxDynamicSharedMemorySize, SMEM_TOTAL);
    cudaFuncSetAttribute(k_gemm_scores, cudaFuncAttributeMaxDynamicSharedMemorySize, SMEM_TOTAL);
    cudaFuncSetAttribute(k_gemm_attn,   cudaFuncAttributeMaxDynamicSharedMemorySize, SD_SMEM);
    cudaFuncSetAttribute(k_gemm_out,    cudaFuncAttributeMaxDynamicSharedMemorySize, SD_SMEM);

    trig_kernel<<<(NSEQ * HALF + 255) / 256, 256>>>();
    scale_kernel<<<BTOK, 256>>>(x, g);
    k_transpose_wuv<<<dim3(UVC / 32, HIDDEN / 32), dim3(32, 8)>>>(Wuv);
    k_transpose_wo<<<dim3(HIDDEN / 32, E_DIM / 32), dim3(32, 8)>>>(Wo);
    k_gemm_uv<<<dim3(UVC / TN, BTOK / TM), 256, SMEM_TOTAL>>>(buv);
    k_transpose_v<<<dim3(E_DIM / 32, NSEQ / 32, NB), dim3(32, 8)>>>();
    rope_kernel<<<BTOK, HALF>>>(gamma, beta);
    k_gemm_scores<<<dim3(NSEQ / TN, NSEQ / TM, NB), 256, SMEM_TOTAL>>>();
    k_gemm_attn<<<dim3(E_DIM / TN, NSEQ / TM, NB), 256, SD_SMEM>>>();
    k_gemm_out<<<dim3(HIDDEN / TN, BTOK / TM), 256, SD_SMEM>>>(x, bo, out);
}

// round 17
// speedup vs baseline: 1.1446x; 1.1423x over previous
#include <cuda_runtime.h>
#include <cuda_bf16.h>
#include <cuda_fp16.h>
#include <cstdint>
#include <math.h>

#define HIDDEN 512
#define E_DIM  1024
#define S_DIM  128
#define NB     32
#define NSEQ   1024
#define BTOK   (NB * NSEQ)
#define UVC    (2 * E_DIM + S_DIM)   // 2176
#define HALF   64

#define TM 128
#define TN 128
#define TKC 32                        // K elements per chunk (2B each)
#define RSTR 64                       // smem row stride (bytes, swizzled)
// bf16 3-term core regions
#define AHI 0
#define ALO 8192
#define BHI 16384
#define BLO 24576
#define BUF_BYTES 32768
#define NSTAGE 3
#define SMEM_TOTAL (NSTAGE * BUF_BYTES)     // 98304
// fp16 single-A dual-B core regions
#define SD_AS  0
#define SD_BH  8192
#define SD_BL  16384
#define SD_BUF 24576
#define SD_SMEM (NSTAGE * SD_BUF)           // 73728

typedef __nv_bfloat16 bf16;
typedef __half        fp16;

// ---------------- scratch (device globals) ---------------------------------
__device__ float g_uv[(size_t)BTOK * UVC];
__device__ fp16  g_xs_h[(size_t)BTOK * HIDDEN];       // normalized x, single fp16
__device__ fp16  g_WuvT_h[(size_t)UVC * HIDDEN];
__device__ fp16  g_WuvT_l[(size_t)UVC * HIDDEN];
__device__ fp16  g_WoT_h[(size_t)HIDDEN * E_DIM];
__device__ fp16  g_WoT_l[(size_t)HIDDEN * E_DIM];
__device__ bf16  g_q_hi[BTOK * S_DIM];
__device__ bf16  g_q_lo[BTOK * S_DIM];
__device__ bf16  g_k_hi[BTOK * S_DIM];
__device__ bf16  g_k_lo[BTOK * S_DIM];
__device__ fp16  g_s_h[(size_t)NB * NSEQ * NSEQ];     // scores, single fp16
__device__ fp16  g_vT_h[(size_t)NB * E_DIM * NSEQ];
__device__ fp16  g_vT_l[(size_t)NB * E_DIM * NSEQ];
__device__ fp16  g_attn_h[(size_t)BTOK * E_DIM];      // attn, single fp16
__device__ float g_sinT[NSEQ * HALF];
__device__ float g_cosT[NSEQ * HALF];

extern __shared__ char dyn_smem[];

// ---------------- PTX helpers ----------------------------------------------
__device__ __forceinline__ uint32_t smem_u32(const void* p) {
    uint32_t a;
    asm("{ .reg .u64 t; cvta.to.shared.u64 t, %1; cvt.u32.u64 %0, t; }"
        : "=r"(a) : "l"(p));
    return a;
}
__device__ __forceinline__ void ldm_x4(uint32_t* r, uint32_t addr) {
    asm volatile("ldmatrix.sync.aligned.m8n8.x4.shared.b16 {%0,%1,%2,%3}, [%4];"
        : "=r"(r[0]), "=r"(r[1]), "=r"(r[2]), "=r"(r[3]) : "r"(addr));
}
__device__ __forceinline__ void mma_bf16(float* d, const uint32_t* a, const uint32_t* b) {
    asm volatile(
        "mma.sync.aligned.m16n8k16.row.col.f32.bf16.bf16.f32 "
        "{%0,%1,%2,%3}, {%4,%5,%6,%7}, {%8,%9}, {%0,%1,%2,%3};"
        : "+f"(d[0]), "+f"(d[1]), "+f"(d[2]), "+f"(d[3])
        : "r"(a[0]), "r"(a[1]), "r"(a[2]), "r"(a[3]), "r"(b[0]), "r"(b[1]));
}
__device__ __forceinline__ void mma_fp16(float* d, const uint32_t* a, const uint32_t* b) {
    asm volatile(
        "mma.sync.aligned.m16n8k16.row.col.f32.f16.f16.f32 "
        "{%0,%1,%2,%3}, {%4,%5,%6,%7}, {%8,%9}, {%0,%1,%2,%3};"
        : "+f"(d[0]), "+f"(d[1]), "+f"(d[2]), "+f"(d[3])
        : "r"(a[0]), "r"(a[1]), "r"(a[2]), "r"(a[3]), "r"(b[0]), "r"(b[1]));
}
#define CP16(dst, src) \
    asm volatile("cp.async.cg.shared.global [%0], [%1], 16;" :: "r"(dst), "l"(src))
#define CP_COMMIT() asm volatile("cp.async.commit_group;" ::: "memory")
#define CP_WAIT(n)  asm volatile("cp.async.wait_group %0;" :: "n"(n) : "memory")

// swizzle: row r, 16B-chunk j -> byte offset within region
__device__ __forceinline__ uint32_t swz_off(int row, int chunk) {
    return (uint32_t)(row * RSTR) + (uint32_t)((chunk ^ ((row >> 1) & 3)) << 4);
}

// fp32 -> bf16 hi/lo
__device__ __forceinline__ void split1(float v, bf16& h, bf16& l) {
    h = __float2bfloat16(v);
    l = __float2bfloat16(v - __bfloat162float(h));
}
// fp32 -> fp16 hi/lo
__device__ __forceinline__ void split1h(float v, fp16& h, fp16& l) {
    h = __float2half(v);
    l = __float2half(v - __half2float(h));
}
__device__ __forceinline__ uint32_t pack_h2(float a, float b) {
    __half2 p = __floats2half2_rn(a, b);
    return *(uint32_t*)&p;
}

// ---------------- core 1: bf16 3-term (A,B both hi/lo) ---------------------
template <class Epi>
__device__ __forceinline__ void gemm_core(const bf16* __restrict__ Ahi,
                                          const bf16* __restrict__ Alo, int lda,
                                          const bf16* __restrict__ Bhi,
                                          const bf16* __restrict__ Blo, int ldb,
                                          int K, Epi epi) {
    const int tid  = threadIdx.x;
    const int lane = tid & 31;
    const int wid  = tid >> 5;
    const int wm   = wid >> 2;
    const int wn   = wid & 3;
    const int g    = lane >> 2;
    const int tg   = lane & 3;
    const int lrow = lane & 15;
    const int lchunk = lane >> 4;
    const uint32_t sbase = smem_u32(dyn_smem);

    const int srow = tid >> 1;
    const int sh   = tid & 1;
    const uint32_t so0 = swz_off(srow, sh * 2);
    const uint32_t so1 = swz_off(srow, sh * 2 + 1);
    const size_t aoff = (size_t)srow * lda + sh * 16;
    const size_t boff = (size_t)srow * ldb + sh * 16;

    float acc[4][4][4];
    #pragma unroll
    for (int i = 0; i < 4; i++)
        #pragma unroll
        for (int j = 0; j < 4; j++)
            #pragma unroll
            for (int t = 0; t < 4; t++) acc[i][j][t] = 0.f;

    const int NC = K / TKC;

    auto stage = [&](int buf, int c) {
        uint32_t d = sbase + buf * BUF_BYTES;
        int ko = c * TKC;
        CP16(d + AHI + so0, Ahi + aoff + ko);
        CP16(d + AHI + so1, Ahi + aoff + ko + 8);
        CP16(d + ALO + so0, Alo + aoff + ko);
        CP16(d + ALO + so1, Alo + aoff + ko + 8);
        CP16(d + BHI + so0, Bhi + boff + ko);
        CP16(d + BHI + so1, Bhi + boff + ko + 8);
        CP16(d + BLO + so0, Blo + boff + ko);
        CP16(d + BLO + so1, Blo + boff + ko + 8);
        CP_COMMIT();
    };

    stage(0, 0);
    if (NC > 1) stage(1, 1);

    int buf = 0;
    for (int c = 0; c < NC; ++c) {
        if (c + 1 < NC) CP_WAIT(1); else CP_WAIT(0);
        __syncthreads();
        if (c + 2 < NC) {
            int nb = buf + 2; if (nb >= NSTAGE) nb -= NSTAGE;
            stage(nb, c + 2);
        }

        const uint32_t cbase = sbase + buf * BUF_BYTES;
        #pragma unroll
        for (int ks = 0; ks < 2; ++ks) {
            const int ch = ks * 2 + lchunk;
            uint32_t bh[4][2], bl[4][2];
            #pragma unroll
            for (int h = 0; h < 2; ++h) {
                uint32_t r4[4];
                ldm_x4(r4, cbase + BHI + swz_off(wn * 32 + h * 16 + lrow, ch));
                bh[2*h][0] = r4[0]; bh[2*h+1][0] = r4[1];
                bh[2*h][1] = r4[2]; bh[2*h+1][1] = r4[3];
                ldm_x4(r4, cbase + BLO + swz_off(wn * 32 + h * 16 + lrow, ch));
                bl[2*h][0] = r4[0]; bl[2*h+1][0] = r4[1];
                bl[2*h][1] = r4[2]; bl[2*h+1][1] = r4[3];
            }
            #pragma unroll
            for (int mt = 0; mt < 4; ++mt) {
                uint32_t ah[4], al[4];
                ldm_x4(ah, cbase + AHI + swz_off(wm * 64 + mt * 16 + lrow, ch));
                ldm_x4(al, cbase + ALO + swz_off(wm * 64 + mt * 16 + lrow, ch));
                #pragma unroll
                for (int nt = 0; nt < 4; ++nt) {
                    mma_bf16(acc[mt][nt], ah, bh[nt]);
                    mma_bf16(acc[mt][nt], ah, bl[nt]);
                    mma_bf16(acc[mt][nt], al, bh[nt]);
                }
            }
        }
        if (++buf >= NSTAGE) buf = 0;
    }

    #pragma unroll
    for (int mt = 0; mt < 4; ++mt) {
        int row0 = wm * 64 + mt * 16 + g;
        #pragma unroll
        for (int nt = 0; nt < 4; ++nt) {
            int col = wn * 32 + nt * 8 + tg * 2;
            epi(row0,     col, acc[mt][nt][0], acc[mt][nt][1]);
            epi(row0 + 8, col, acc[mt][nt][2], acc[mt][nt][3]);
        }
    }
}

// ---------------- core 2: fp16 single-A x dual-B (2 MMAs per pair) ---------
// C = A * (Bh + Bl)^T  — exact except A's fp16 quantization.
template <class Epi>
__device__ __forceinline__ void gemm_core_sd(const fp16* __restrict__ A, int lda,
                                             const fp16* __restrict__ Bh,
                                             const fp16* __restrict__ Bl, int ldb,
                                             int K, Epi epi) {
    const int tid  = threadIdx.x;
    const int lane = tid & 31;
    const int wid  = tid >> 5;
    const int wm   = wid >> 2;
    const int wn   = wid & 3;
    const int g    = lane >> 2;
    const int tg   = lane & 3;
    const int lrow = lane & 15;
    const int lchunk = lane >> 4;
    const uint32_t sbase = smem_u32(dyn_smem);

    const int srow = tid >> 1;
    const int sh   = tid & 1;
    const uint32_t so0 = swz_off(srow, sh * 2);
    const uint32_t so1 = swz_off(srow, sh * 2 + 1);
    const size_t aoff = (size_t)srow * lda + sh * 16;
    const size_t boff = (size_t)srow * ldb + sh * 16;

    float acc[4][4][4];
    #pragma unroll
    for (int i = 0; i < 4; i++)
        #pragma unroll
        for (int j = 0; j < 4; j++)
            #pragma unroll
            for (int t = 0; t < 4; t++) acc[i][j][t] = 0.f;

    const int NC = K / TKC;

    auto stage = [&](int buf, int c) {
        uint32_t d = sbase + buf * SD_BUF;
        int ko = c * TKC;
        CP16(d + SD_AS + so0, A + aoff + ko);
        CP16(d + SD_AS + so1, A + aoff + ko + 8);
        CP16(d + SD_BH + so0, Bh + boff + ko);
        CP16(d + SD_BH + so1, Bh + boff + ko + 8);
        CP16(d + SD_BL + so0, Bl + boff + ko);
        CP16(d + SD_BL + so1, Bl + boff + ko + 8);
        CP_COMMIT();
    };

    stage(0, 0);
    if (NC > 1) stage(1, 1);

    int buf = 0;
    for (int c = 0; c < NC; ++c) {
        if (c + 1 < NC) CP_WAIT(1); else CP_WAIT(0);
        __syncthreads();
        if (c + 2 < NC) {
            int nb = buf + 2; if (nb >= NSTAGE) nb -= NSTAGE;
            stage(nb, c + 2);
        }

        const uint32_t cbase = sbase + buf * SD_BUF;
        #pragma unroll
        for (int ks = 0; ks < 2; ++ks) {
            const int ch = ks * 2 + lchunk;
            uint32_t bh[4][2], bl[4][2];
            #pragma unroll
            for (int h = 0; h < 2; ++h) {
                uint32_t r4[4];
                ldm_x4(r4, cbase + SD_BH + swz_off(wn * 32 + h * 16 + lrow, ch));
                bh[2*h][0] = r4[0]; bh[2*h+1][0] = r4[1];
                bh[2*h][1] = r4[2]; bh[2*h+1][1] = r4[3];
                ldm_x4(r4, cbase + SD_BL + swz_off(wn * 32 + h * 16 + lrow, ch));
                bl[2*h][0] = r4[0]; bl[2*h+1][0] = r4[1];
                bl[2*h][1] = r4[2]; bl[2*h+1][1] = r4[3];
            }
            #pragma unroll
            for (int mt = 0; mt < 4; ++mt) {
                uint32_t ah[4];
                ldm_x4(ah, cbase + SD_AS + swz_off(wm * 64 + mt * 16 + lrow, ch));
                #pragma unroll
                for (int nt = 0; nt < 4; ++nt) {
                    mma_fp16(acc[mt][nt], ah, bh[nt]);
                    mma_fp16(acc[mt][nt], ah, bl[nt]);
                }
            }
        }
        if (++buf >= NSTAGE) buf = 0;
    }

    #pragma unroll
    for (int mt = 0; mt < 4; ++mt) {
        int row0 = wm * 64 + mt * 16 + g;
        #pragma unroll
        for (int nt = 0; nt < 4; ++nt) {
            int col = wn * 32 + nt * 8 + tg * 2;
            epi(row0,     col, acc[mt][nt][0], acc[mt][nt][1]);
            epi(row0 + 8, col, acc[mt][nt][2], acc[mt][nt][3]);
        }
    }
}

// ---------------- GEMM kernels ---------------------------------------------
struct EpiUV {
    const float* buv; int bm, bn;
    __device__ __forceinline__ void operator()(int r, int c, float a, float b) const {
        float va = a + buv[bn + c];
        float vb = b + buv[bn + c + 1];
        float* p = g_uv + (size_t)(bm + r) * UVC + bn + c;
        p[0] = va / (1.0f + __expf(-va));
        p[1] = vb / (1.0f + __expf(-vb));
    }
};
__global__ __launch_bounds__(256, 2) void k_gemm_uv(const float* __restrict__ buv) {
    const int bm = blockIdx.y * TM, bn = blockIdx.x * TN;
    gemm_core_sd(g_xs_h + (size_t)bm * HIDDEN, HIDDEN,
                 g_WuvT_h + (size_t)bn * HIDDEN, g_WuvT_l + (size_t)bn * HIDDEN, HIDDEN,
                 HIDDEN, EpiUV{buv, bm, bn});
}

struct EpiScores {
    int b, bm, bn;
    __device__ __forceinline__ void operator()(int r, int c, float a, float bb) const {
        float wa = fmaxf(a  * 0.08838834764831845f, 0.f);
        float wb = fmaxf(bb * 0.08838834764831845f, 0.f);
        size_t off = (size_t)b * NSEQ * NSEQ + (size_t)(bm + r) * NSEQ + bn + c;
        *(uint32_t*)(g_s_h + off) = pack_h2(wa * wa, wb * wb);
    }
};
__global__ __launch_bounds__(256, 2) void k_gemm_scores() {
    const int b = blockIdx.z;
    const int bm = blockIdx.y * TM, bn = blockIdx.x * TN;
    size_t qa = (size_t)(b * NSEQ + bm) * S_DIM;
    size_t kb = (size_t)(b * NSEQ + bn) * S_DIM;
    gemm_core(g_q_hi + qa, g_q_lo + qa, S_DIM,
              g_k_hi + kb, g_k_lo + kb, S_DIM, S_DIM,
              EpiScores{b, bm, bn});
}

struct EpiAttn {
    int b, bm, bn;
    __device__ __forceinline__ void operator()(int r, int c, float a, float bvv) const {
        size_t tok = (size_t)b * NSEQ + bm + r;
        const float* u = g_uv + tok * UVC + bn + c;
        *(uint32_t*)(g_attn_h + tok * E_DIM + bn + c) = pack_h2(a * u[0], bvv * u[1]);
    }
};
__global__ __launch_bounds__(256, 2) void k_gemm_attn() {
    const int b = blockIdx.z;
    const int bm = blockIdx.y * TM, bn = blockIdx.x * TN;
    size_t sa = (size_t)b * NSEQ * NSEQ + (size_t)bm * NSEQ;
    size_t vb = (size_t)b * E_DIM * NSEQ + (size_t)bn * NSEQ;
    gemm_core_sd(g_s_h + sa, NSEQ,
                 g_vT_h + vb, g_vT_l + vb, NSEQ, NSEQ,
                 EpiAttn{b, bm, bn});
}

struct EpiOut {
    const float* x; const float* bo; float* out; int bm, bn;
    __device__ __forceinline__ void operator()(int r, int c, float a, float b) const {
        size_t row = bm + r;
        int col = bn + c;
        out[row * HIDDEN + col]     = a + bo[col]     + x[row * HIDDEN + col];
        out[row * HIDDEN + col + 1] = b + bo[col + 1] + x[row * HIDDEN + col + 1];
    }
};
__global__ __launch_bounds__(256, 2) void k_gemm_out(const float* __restrict__ x,
                                                     const float* __restrict__ bo,
                                                     float* __restrict__ out) {
    const int bm = blockIdx.y * TM, bn = blockIdx.x * TN;
    gemm_core_sd(g_attn_h + (size_t)bm * E_DIM, E_DIM,
                 g_WoT_h + (size_t)bn * E_DIM, g_WoT_l + (size_t)bn * E_DIM, E_DIM,
                 E_DIM, EpiOut{x, bo, out, bm, bn});
}

// ---------------- transposes -----------------------------------------------
__global__ void k_transpose_wuv(const float* __restrict__ Wuv) {
    __shared__ float t[32][33];
    int c0 = blockIdx.x * 32, r0 = blockIdx.y * 32;
    int tx = threadIdx.x, ty = threadIdx.y;
    #pragma unroll
    for (int j = 0; j < 32; j += 8)
        t[ty + j][tx] = Wuv[(size_t)(r0 + ty + j) * UVC + c0 + tx];
    __syncthreads();
    #pragma unroll
    for (int j = 0; j < 32; j += 8) {
        fp16 h, l;
        split1h(t[tx][ty + j], h, l);
        size_t off = (size_t)(c0 + ty + j) * HIDDEN + r0 + tx;
        g_WuvT_h[off] = h;
        g_WuvT_l[off] = l;
    }
}
__global__ void k_transpose_wo(const float* __restrict__ Wo) {
    __shared__ float t[32][33];
    int c0 = blockIdx.x * 32, r0 = blockIdx.y * 32;
    int tx = threadIdx.x, ty = threadIdx.y;
    #pragma unroll
    for (int j = 0; j < 32; j += 8)
        t[ty + j][tx] = Wo[(size_t)(r0 + ty + j) * HIDDEN + c0 + tx];
    __syncthreads();
    #pragma unroll
    for (int j = 0; j < 32; j += 8) {
        fp16 h, l;
        split1h(t[tx][ty + j], h, l);
        size_t off = (size_t)(c0 + ty + j) * E_DIM + r0 + tx;
        g_WoT_h[off] = h;
        g_WoT_l[off] = l;
    }
}
__global__ void k_transpose_v() {
    __shared__ float t[32][33];
    int b = blockIdx.z;
    const float* src = g_uv + (size_t)b * NSEQ * UVC + E_DIM;
    fp16* dh = g_vT_h + (size_t)b * E_DIM * NSEQ;
    fp16* dl = g_vT_l + (size_t)b * E_DIM * NSEQ;
    int c0 = blockIdx.x * 32, r0 = blockIdx.y * 32;
    int tx = threadIdx.x, ty = threadIdx.y;
    #pragma unroll
    for (int j = 0; j < 32; j += 8)
        t[ty + j][tx] = src[(size_t)(r0 + ty + j) * UVC + c0 + tx];
    __syncthreads();
    #pragma unroll
    for (int j = 0; j < 32; j += 8) {
        fp16 h, l;
        split1h(t[tx][ty + j], h, l);
        size_t off = (size_t)(c0 + ty + j) * NSEQ + r0 + tx;
        dh[off] = h;
        dl[off] = l;
    }
}

// ---------------- small kernels --------------------------------------------
__global__ void trig_kernel() {
    int t = blockIdx.x * blockDim.x + threadIdx.x;
    if (t >= NSEQ * HALF) return;
    int pos = t >> 6;
    int j = t & 63;
    double freq_d = pow(10000.0, (double)j / 64.0);
    float freq_f = (float)freq_d;
    float arg = __fmul_rn((float)pos, freq_f);
    double a = (double)arg;
    g_sinT[t] = (float)sin(a);
    g_cosT[t] = (float)cos(a);
}

__global__ void scale_kernel(const float* __restrict__ x, const float* __restrict__ g) {
    int m = blockIdx.x;
    const float* xr = x + (size_t)m * HIDDEN;
    float ss = 0.f;
    for (int i = threadIdx.x; i < HIDDEN; i += 256) {
        float v = xr[i];
        ss = fmaf(v, v, ss);
    }
    #pragma unroll
    for (int o = 16; o; o >>= 1) ss += __shfl_xor_sync(0xffffffffu, ss, o);
    __shared__ float red[8];
    __shared__ float s_sh;
    if ((threadIdx.x & 31) == 0) red[threadIdx.x >> 5] = ss;
    __syncthreads();
    if (threadIdx.x == 0) {
        float t = 0.f;
        #pragma unroll
        for (int i = 0; i < 8; i++) t += red[i];
        float norm = sqrtf(t) * 0.04419417382415922f;
        s_sh = g[0] / fmaxf(norm, 1e-5f);
    }
    __syncthreads();
    float s = s_sh;
    int i2 = threadIdx.x * 2;
    float2 v = *(const float2*)(xr + i2);
    *(uint32_t*)(g_xs_h + (size_t)m * HIDDEN + i2) = pack_h2(v.x * s, v.y * s);
}

__global__ void rope_kernel(const float* __restrict__ gamma, const float* __restrict__ beta) {
    int m = blockIdx.x;
    int j = threadIdx.x;
    int pos = m & (NSEQ - 1);
    const float* base = g_uv + (size_t)m * UVC + 2 * E_DIM;
    float b1 = base[j];
    float b2 = base[j + HALF];
    float c = g_cosT[pos * HALF + j];
    float sn = g_sinT[pos * HALF + j];
    float q1 = b1 * gamma[j] + beta[j];
    float q2 = b2 * gamma[j + HALF] + beta[j + HALF];
    float k1 = b1 * gamma[S_DIM + j] + beta[S_DIM + j];
    float k2 = b2 * gamma[S_DIM + j + HALF] + beta[S_DIM + j + HALF];
    float qa = q1 * c - q2 * sn, qb = q2 * c + q1 * sn;
    float ka = k1 * c - k2 * sn, kb = k2 * c + k1 * sn;
    bf16 h, l;
    int o = m * S_DIM + j;
    split1(qa, h, l); g_q_hi[o] = h;        g_q_lo[o] = l;
    split1(qb, h, l); g_q_hi[o + HALF] = h; g_q_lo[o + HALF] = l;
    split1(ka, h, l); g_k_hi[o] = h;        g_k_lo[o] = l;
    split1(kb, h, l); g_k_hi[o + HALF] = h; g_k_lo[o + HALF] = l;
}

// ---------------- launcher -------------------------------------------------
extern "C" void kernel_launch(void* const* d_in, const int* in_sizes, int n_in,
                              void* d_out, int out_size) {
    const float* x     = (const float*)d_in[0];
    const float* Wuv   = (const float*)d_in[1];
    const float* buv   = (const float*)d_in[2];
    const float* gamma = (const float*)d_in[3];
    const float* beta  = (const float*)d_in[4];
    const float* Wo    = (const float*)d_in[5];
    const float* bo    = (const float*)d_in[6];
    const float* g     = (const float*)d_in[7];
    float* out = (float*)d_out;

    cudaFuncSetAttribute(k_gemm_uv,     cudaFuncAttributeMaxDynamicSharedMemorySize, SD_SMEM);
    cudaFuncSetAttribute(k_gemm_scores, cudaFuncAttributeMaxDynamicSharedMemorySize, SMEM_TOTAL);
    cudaFuncSetAttribute(k_gemm_attn,   cudaFuncAttributeMaxDynamicSharedMemorySize, SD_SMEM);
    cudaFuncSetAttribute(k_gemm_out,    cudaFuncAttributeMaxDynamicSharedMemorySize, SD_SMEM);

    trig_kernel<<<(NSEQ * HALF + 255) / 256, 256>>>();
    scale_kernel<<<BTOK, 256>>>(x, g);
    k_transpose_wuv<<<dim3(UVC / 32, HIDDEN / 32), dim3(32, 8)>>>(Wuv);
    k_transpose_wo<<<dim3(HIDDEN / 32, E_DIM / 32), dim3(32, 8)>>>(Wo);
    k_gemm_uv<<<dim3(UVC / TN, BTOK / TM), 256, SD_SMEM>>>(buv);
    k_transpose_v<<<dim3(E_DIM / 32, NSEQ / 32, NB), dim3(32, 8)>>>();
    rope_kernel<<<BTOK, HALF>>>(gamma, beta);
    k_gemm_scores<<<dim3(NSEQ / TN, NSEQ / TM, NB), 256, SMEM_TOTAL>>>();
    k_gemm_attn<<<dim3(E_DIM / TN, NSEQ / TM, NB), 256, SD_SMEM>>>();
    k_gemm_out<<<dim3(HIDDEN / TN, BTOK / TM), 256, SD_SMEM>>>(x, bo, out);
}